// round 14
// baseline (speedup 1.0000x reference)
#include <cuda_runtime.h>
#include <cuda_fp16.h>
#include <cstdint>
#include <cstddef>

#define IN_F   4096
#define OUT_F  11008
#define M_DIM  8192
#define K_DIM  4096
#define N_DIM  11008

#define BM 128
#define BN 256
#define BK 64
#define NSTAGE 3
#define NTHREADS 256
#define ASTR 72                 // BK + 8 halfword skew
#define ROWB (ASTR * 2)         // 144 B rows (144%128=16 -> conflict-free ldmatrix)

#define NTILE (N_DIM / BN)      // 43
#define MTILE (M_DIM / BM)      // 64
#define GRP 8                   // M-panel raster

#define A_STAGE_BYTES (BM * ROWB)           // 18432
#define B_STAGE_BYTES (BN * ROWB)           // 36864
#define B_BASE (NSTAGE * A_STAGE_BYTES)
#define SMEM_BYTES (NSTAGE * (A_STAGE_BYTES + B_STAGE_BYTES))  // 165888

__constant__ float c_nf4[16] = {
    -1.0f, -0.6961928009986877f, -0.5250730514526367f, -0.39491748809814453f,
    -0.28444138169288635f, -0.18477343022823334f, -0.09105003625154495f, 0.0f,
    0.07958029955625534f, 0.16093020141124725f, 0.24611230194568634f,
    0.33791524171829224f, 0.44070982933044434f, 0.5626170039176941f,
    0.7229568362236023f, 1.0f };

__device__ __align__(16) __half g_W[(size_t)OUT_F * IN_F];
__device__ __align__(16) __half g_X[(size_t)M_DIM * K_DIM];

// ---------------------------------------------------------------------------
// Kernel 1: NF4 dequant via shared-mem LUT (78% DRAM, at roofline).
// ---------------------------------------------------------------------------
__global__ void dequant_w_kernel(const int* __restrict__ codes,
                                 const float* __restrict__ absmax) {
    __shared__ float lut[16];
    if (threadIdx.x < 16) lut[threadIdx.x] = c_nf4[threadIdx.x];
    __syncthreads();
    size_t t = (size_t)blockIdx.x * blockDim.x + threadIdx.x;
    const size_t total8 = (size_t)OUT_F * IN_F / 8;
    if (t >= total8) return;
    float am = absmax[t >> 3];
    int4 c0 = ((const int4*)codes)[2 * t];
    int4 c1 = ((const int4*)codes)[2 * t + 1];
    __half h[8];
    h[0] = __float2half(lut[c0.x] * am);
    h[1] = __float2half(lut[c0.y] * am);
    h[2] = __float2half(lut[c0.z] * am);
    h[3] = __float2half(lut[c0.w] * am);
    h[4] = __float2half(lut[c1.x] * am);
    h[5] = __float2half(lut[c1.y] * am);
    h[6] = __float2half(lut[c1.z] * am);
    h[7] = __float2half(lut[c1.w] * am);
    ((uint4*)g_W)[t] = *(const uint4*)h;
}

// ---------------------------------------------------------------------------
// Kernel 2: x fp32 -> fp16
// ---------------------------------------------------------------------------
__global__ void convert_x_kernel(const float* __restrict__ x) {
    size_t t = (size_t)blockIdx.x * blockDim.x + threadIdx.x;
    const size_t total8 = (size_t)M_DIM * K_DIM / 8;
    if (t >= total8) return;
    float4 a = ((const float4*)x)[2 * t];
    float4 b = ((const float4*)x)[2 * t + 1];
    __half h[8];
    h[0] = __float2half(a.x); h[1] = __float2half(a.y);
    h[2] = __float2half(a.z); h[3] = __float2half(a.w);
    h[4] = __float2half(b.x); h[5] = __float2half(b.y);
    h[6] = __float2half(b.z); h[7] = __float2half(b.w);
    ((uint4*)g_X)[t] = *(const uint4*)h;
}

// ---------------------------------------------------------------------------
// Kernel 3: fp16 GEMM. CTA 128x256xBK64, 256 thr, 8 warps (2m x 4n),
// warp tile 64x64. LDSM/HMMA = 0.25; 128 HMMA per barrier pair per warp.
// ---------------------------------------------------------------------------
__device__ __forceinline__ void cp16(uint32_t daddr, const void* src) {
    asm volatile("cp.async.cg.shared.global [%0], [%1], 16;" :: "r"(daddr), "l"(src) : "memory");
}

__device__ __forceinline__ uint32_t smem_u32(const void* p) {
    uint32_t a;
    asm("{ .reg .u64 t; cvta.to.shared.u64 t, %1; cvt.u32.u64 %0, t; }" : "=r"(a) : "l"(p));
    return a;
}

// stage the kt-th K-slice: A 128 rows + B 256 rows, 8 x 16B chunks per row
__device__ __forceinline__ void produce_stage(uint32_t sa, uint32_t sb,
                                              const __half* Ag, const __half* Bg,
                                              int kt, int tid) {
    const __half* a = Ag + (size_t)kt * BK;
    const __half* b = Bg + (size_t)kt * BK;
#pragma unroll
    for (int j = 0; j < 4; ++j) {               // A: 128 rows * 8 chunks = 1024
        int ch = tid + j * NTHREADS;
        int r = ch >> 3, c = ch & 7;
        cp16(sa + r * ROWB + c * 16, a + (size_t)r * K_DIM + c * 8);
    }
#pragma unroll
    for (int j = 0; j < 8; ++j) {               // B: 256 rows * 8 chunks = 2048
        int ch = tid + j * NTHREADS;
        int r = ch >> 3, c = ch & 7;
        cp16(sb + r * ROWB + c * 16, b + (size_t)r * K_DIM + c * 8);
    }
    asm volatile("cp.async.commit_group;" ::: "memory");
}

__global__ void __launch_bounds__(NTHREADS, 1) gemm_f16_kernel(float* __restrict__ out) {
    extern __shared__ char smem[];
    const uint32_t sbase = smem_u32(smem);

    const int tid  = threadIdx.x;
    const int lane = tid & 31;
    const int warp = tid >> 5;
    const int wm   = warp >> 2;      // 0..1  (64-row band)
    const int wn   = warp & 3;       // 0..3  (64-col band)

    // M-panel raster
    const int bid   = blockIdx.x;
    const int panel = bid / (GRP * NTILE);
    const int rem   = bid % (GRP * NTILE);
    const int bn    = rem / GRP;
    const int bm    = panel * GRP + (rem % GRP);

    const size_t bm0 = (size_t)bm * BM;
    const size_t bn0 = (size_t)bn * BN;
    const __half* Ag = g_X + bm0 * K_DIM;
    const __half* Bg = g_W + bn0 * K_DIM;

    float c[4][8][4];
#pragma unroll
    for (int i = 0; i < 4; ++i)
#pragma unroll
        for (int j = 0; j < 8; ++j)
#pragma unroll
            for (int r = 0; r < 4; ++r) c[i][j][r] = 0.0f;

    produce_stage(sbase, sbase + B_BASE, Ag, Bg, 0, tid);
    produce_stage(sbase + A_STAGE_BYTES, sbase + B_BASE + B_STAGE_BYTES, Ag, Bg, 1, tid);

    const int NKT = K_DIM / BK;   // 64

    const int a_row = wm * 64 + (lane & 15);                         // + mi*16
    const int a_kof = (lane >> 4) * 8;
    const int b_row = wn * 64 + (lane & 7) + ((lane >> 4) & 1) * 8;  // + ni2*16
    const int b_kof = ((lane >> 3) & 1) * 8;

    for (int i = 0; i < NKT; ++i) {
        asm volatile("cp.async.wait_group 1;" ::: "memory");
        __syncthreads();

        if (i + 2 < NKT) {
            int nb = (i + 2) % NSTAGE;
            produce_stage(sbase + nb * A_STAGE_BYTES,
                          sbase + B_BASE + nb * B_STAGE_BYTES, Ag, Bg, i + 2, tid);
        }

        const int buf = i % NSTAGE;
        const uint32_t sa = sbase + buf * A_STAGE_BYTES;
        const uint32_t sb = sbase + B_BASE + buf * B_STAGE_BYTES;

#pragma unroll
        for (int ks = 0; ks < 4; ++ks) {
            const int k0 = ks * 16;
            uint32_t af[4][4];
            uint32_t bf[8][2];
#pragma unroll
            for (int mi = 0; mi < 4; ++mi) {
                uint32_t addr = sa + (a_row + mi * 16) * ROWB + (k0 + a_kof) * 2;
                asm volatile("ldmatrix.sync.aligned.m8n8.x4.shared.b16 {%0,%1,%2,%3}, [%4];"
                             : "=r"(af[mi][0]), "=r"(af[mi][1]), "=r"(af[mi][2]), "=r"(af[mi][3])
                             : "r"(addr));
            }
#pragma unroll
            for (int ni2 = 0; ni2 < 4; ++ni2) {
                uint32_t addr = sb + (b_row + ni2 * 16) * ROWB + (k0 + b_kof) * 2;
                asm volatile("ldmatrix.sync.aligned.m8n8.x4.shared.b16 {%0,%1,%2,%3}, [%4];"
                             : "=r"(bf[2 * ni2][0]), "=r"(bf[2 * ni2][1]),
                               "=r"(bf[2 * ni2 + 1][0]), "=r"(bf[2 * ni2 + 1][1])
                             : "r"(addr));
            }
#pragma unroll
            for (int mi = 0; mi < 4; ++mi) {
#pragma unroll
                for (int ni = 0; ni < 8; ++ni) {
                    asm volatile(
                        "mma.sync.aligned.m16n8k16.row.col.f32.f16.f16.f32 "
                        "{%0,%1,%2,%3}, {%4,%5,%6,%7}, {%8,%9}, {%0,%1,%2,%3};"
                        : "+f"(c[mi][ni][0]), "+f"(c[mi][ni][1]),
                          "+f"(c[mi][ni][2]), "+f"(c[mi][ni][3])
                        : "r"(af[mi][0]), "r"(af[mi][1]), "r"(af[mi][2]), "r"(af[mi][3]),
                          "r"(bf[ni][0]), "r"(bf[ni][1]));
                }
            }
        }
    }

    // epilogue: direct fp32 float2 stores
#pragma unroll
    for (int mi = 0; mi < 4; ++mi) {
        const int r0 = (int)bm0 + wm * 64 + mi * 16 + (lane >> 2);
#pragma unroll
        for (int ni = 0; ni < 8; ++ni) {
            const int col = (int)bn0 + wn * 64 + ni * 8 + (lane & 3) * 2;
            *(float2*)&out[(size_t)r0 * N_DIM + col] =
                make_float2(c[mi][ni][0], c[mi][ni][1]);
            *(float2*)&out[(size_t)(r0 + 8) * N_DIM + col] =
                make_float2(c[mi][ni][2], c[mi][ni][3]);
        }
    }
}

// ---------------------------------------------------------------------------
extern "C" void kernel_launch(void* const* d_in, const int* in_sizes, int n_in,
                              void* d_out, int out_size) {
    const float* x      = (const float*)d_in[0];
    const int*   codes  = (const int*)d_in[1];
    const float* absmax = (const float*)d_in[2];
    float*       out    = (float*)d_out;

    {
        size_t t8 = (size_t)OUT_F * IN_F / 8;
        dequant_w_kernel<<<(unsigned)((t8 + 255) / 256), 256>>>(codes, absmax);
    }
    {
        size_t t8 = (size_t)M_DIM * K_DIM / 8;
        convert_x_kernel<<<(unsigned)((t8 + 255) / 256), 256>>>(x);
    }
    cudaFuncSetAttribute(gemm_f16_kernel,
                         cudaFuncAttributeMaxDynamicSharedMemorySize, SMEM_BYTES);
    gemm_f16_kernel<<<NTILE * MTILE, NTHREADS, SMEM_BYTES>>>(out);
}

// round 16
// speedup vs baseline: 1.7152x; 1.7152x over previous
#include <cuda_runtime.h>
#include <cuda_fp16.h>
#include <cstdint>
#include <cstddef>

#define IN_F   4096
#define OUT_F  11008
#define M_DIM  8192
#define K_DIM  4096
#define N_DIM  11008

#define BM 128
#define BN 128
#define BK 64
#define NSTAGE 3
#define ASTR 72                 // BK + 8 halfword skew
#define ROWB (ASTR * 2)         // 144 B rows (rows hit distinct 16B banks mod 128)

#define NTILE (N_DIM / BN)      // 86
#define MTILE (M_DIM / BM)      // 64
#define GRP 8                   // M-panel raster

#define A_STAGE_BYTES (BM * ROWB)           // 18432
#define B_STAGE_BYTES (BN * ROWB)           // 18432
#define B_BASE (NSTAGE * A_STAGE_BYTES)
#define SMEM_BYTES (NSTAGE * (A_STAGE_BYTES + B_STAGE_BYTES))  // 110592 (x2 CTA fits 228KB)

#define W_T8 ((size_t)OUT_F * IN_F / 8)     // 5636096
#define X_T8 ((size_t)M_DIM * K_DIM / 8)    // 4194304

__constant__ float c_nf4[16] = {
    -1.0f, -0.6961928009986877f, -0.5250730514526367f, -0.39491748809814453f,
    -0.28444138169288635f, -0.18477343022823334f, -0.09105003625154495f, 0.0f,
    0.07958029955625534f, 0.16093020141124725f, 0.24611230194568634f,
    0.33791524171829224f, 0.44070982933044434f, 0.5626170039176941f,
    0.7229568362236023f, 1.0f };

__device__ __align__(16) __half g_W[(size_t)OUT_F * IN_F];
__device__ __align__(16) __half g_X[(size_t)M_DIM * K_DIM];

// ---------------------------------------------------------------------------
// Kernel 1: fused prep — NF4 dequant (shared LUT) + x fp32->fp16.
// Independent element ranges; one launch, overlapped tails.
// ---------------------------------------------------------------------------
__global__ void prep_kernel(const float* __restrict__ x,
                            const int* __restrict__ codes,
                            const float* __restrict__ absmax) {
    __shared__ float lut[16];
    if (threadIdx.x < 16) lut[threadIdx.x] = c_nf4[threadIdx.x];
    __syncthreads();
    size_t t = (size_t)blockIdx.x * blockDim.x + threadIdx.x;
    if (t < W_T8) {
        float am = absmax[t >> 3];
        int4 c0 = ((const int4*)codes)[2 * t];
        int4 c1 = ((const int4*)codes)[2 * t + 1];
        __half h[8];
        h[0] = __float2half(lut[c0.x] * am);
        h[1] = __float2half(lut[c0.y] * am);
        h[2] = __float2half(lut[c0.z] * am);
        h[3] = __float2half(lut[c0.w] * am);
        h[4] = __float2half(lut[c1.x] * am);
        h[5] = __float2half(lut[c1.y] * am);
        h[6] = __float2half(lut[c1.z] * am);
        h[7] = __float2half(lut[c1.w] * am);
        ((uint4*)g_W)[t] = *(const uint4*)h;
    } else {
        size_t u = t - W_T8;
        if (u < X_T8) {
            float4 a = ((const float4*)x)[2 * u];
            float4 b = ((const float4*)x)[2 * u + 1];
            __half h[8];
            h[0] = __float2half(a.x); h[1] = __float2half(a.y);
            h[2] = __float2half(a.z); h[3] = __float2half(a.w);
            h[4] = __float2half(b.x); h[5] = __float2half(b.y);
            h[6] = __float2half(b.z); h[7] = __float2half(b.w);
            ((uint4*)g_X)[u] = *(const uint4*)h;
        }
    }
}

// ---------------------------------------------------------------------------
// Kernel 2: fp16 GEMM. 128x128xBK64, 256 thr, 8 warps (2m x 4n), 2 CTA/SM,
// 3-stage cp.async ring + two-slot register fragment pipeline.
// ---------------------------------------------------------------------------
__device__ __forceinline__ void cp16(uint32_t daddr, const void* src) {
    asm volatile("cp.async.cg.shared.global [%0], [%1], 16;" :: "r"(daddr), "l"(src) : "memory");
}

__device__ __forceinline__ uint32_t smem_u32(const void* p) {
    uint32_t a;
    asm("{ .reg .u64 t; cvta.to.shared.u64 t, %1; cvt.u32.u64 %0, t; }" : "=r"(a) : "l"(p));
    return a;
}

__device__ __forceinline__ void produce_stage(uint32_t sa, uint32_t sb,
                                              const __half* Ag, const __half* Bg,
                                              int kt, int tid) {
    const __half* a = Ag + (size_t)kt * BK;
    const __half* b = Bg + (size_t)kt * BK;
#pragma unroll
    for (int j = 0; j < 4; ++j) {
        int ch = tid + j * 256;
        int r = ch >> 3, c = ch & 7;
        cp16(sa + r * ROWB + c * 16, a + (size_t)r * K_DIM + c * 8);
    }
#pragma unroll
    for (int j = 0; j < 4; ++j) {
        int ch = tid + j * 256;
        int r = ch >> 3, c = ch & 7;
        cp16(sb + r * ROWB + c * 16, b + (size_t)r * K_DIM + c * 8);
    }
    asm volatile("cp.async.commit_group;" ::: "memory");
}

#define LDFRAG(slot, koff)                                                        \
    do {                                                                          \
        _Pragma("unroll")                                                         \
        for (int mi = 0; mi < 4; ++mi) {                                          \
            asm volatile("ldmatrix.sync.aligned.m8n8.x4.shared.b16 "              \
                         "{%0,%1,%2,%3}, [%4];"                                   \
                         : "=r"(af[slot][mi][0]), "=r"(af[slot][mi][1]),          \
                           "=r"(af[slot][mi][2]), "=r"(af[slot][mi][3])           \
                         : "r"(aaddr[mi] + (koff)));                              \
        }                                                                         \
        _Pragma("unroll")                                                         \
        for (int ni2 = 0; ni2 < 2; ++ni2) {                                       \
            asm volatile("ldmatrix.sync.aligned.m8n8.x4.shared.b16 "              \
                         "{%0,%1,%2,%3}, [%4];"                                   \
                         : "=r"(bf[slot][2 * ni2][0]), "=r"(bf[slot][2 * ni2][1]),\
                           "=r"(bf[slot][2 * ni2 + 1][0]),                        \
                           "=r"(bf[slot][2 * ni2 + 1][1])                         \
                         : "r"(baddr[ni2] + (koff)));                             \
        }                                                                         \
    } while (0)

__global__ void __launch_bounds__(256, 2) gemm_f16_kernel(float* __restrict__ out) {
    extern __shared__ char smem[];
    const uint32_t sbase = smem_u32(smem);

    const int tid  = threadIdx.x;
    const int lane = tid & 31;
    const int warp = tid >> 5;
    const int wm   = warp >> 2;      // 0..1
    const int wn   = warp & 3;       // 0..3

    const int bid   = blockIdx.x;
    const int panel = bid / (GRP * NTILE);
    const int rem   = bid % (GRP * NTILE);
    const int bn    = rem / GRP;
    const int bm    = panel * GRP + (rem % GRP);

    const size_t bm0 = (size_t)bm * BM;
    const size_t bn0 = (size_t)bn * BN;
    const __half* Ag = g_X + bm0 * K_DIM;
    const __half* Bg = g_W + bn0 * K_DIM;

    float c[4][4][4];
#pragma unroll
    for (int i = 0; i < 4; ++i)
#pragma unroll
        for (int j = 0; j < 4; ++j)
#pragma unroll
            for (int r = 0; r < 4; ++r) c[i][j][r] = 0.0f;

    produce_stage(sbase, sbase + B_BASE, Ag, Bg, 0, tid);
    produce_stage(sbase + A_STAGE_BYTES, sbase + B_BASE + B_STAGE_BYTES, Ag, Bg, 1, tid);

    const int NKT = K_DIM / BK;   // 64

    // per-fragment base offsets within a stage (bytes)
    const int a_off = (wm * 64 + (lane & 15)) * ROWB + (lane >> 4) * 16;
    const int b_off = (wn * 32 + (lane & 7) + ((lane >> 4) & 1) * 8) * ROWB
                      + ((lane >> 3) & 1) * 16;

    for (int i = 0; i < NKT; ++i) {
        asm volatile("cp.async.wait_group 1;" ::: "memory");
        __syncthreads();

        if (i + 2 < NKT) {
            int nb = (i + 2) % NSTAGE;
            produce_stage(sbase + nb * A_STAGE_BYTES,
                          sbase + B_BASE + nb * B_STAGE_BYTES, Ag, Bg, i + 2, tid);
        }

        const int buf = i % NSTAGE;
        const uint32_t sa = sbase + buf * A_STAGE_BYTES;
        const uint32_t sb = sbase + B_BASE + buf * B_STAGE_BYTES;

        uint32_t aaddr[4], baddr[2];
#pragma unroll
        for (int mi = 0; mi < 4; ++mi) aaddr[mi] = sa + a_off + mi * 16 * ROWB;
#pragma unroll
        for (int ni2 = 0; ni2 < 2; ++ni2) baddr[ni2] = sb + b_off + ni2 * 16 * ROWB;

        uint32_t af[2][4][4];
        uint32_t bf[2][4][2];

        LDFRAG(0, 0);                 // ks=0 fragments

#pragma unroll
        for (int ks = 0; ks < 4; ++ks) {
            const int cur = ks & 1;
            if (ks < 3) {
                const int nxt = cur ^ 1;
                LDFRAG(nxt, (ks + 1) * 32);   // prefetch ks+1 under ks HMMAs
            }
#pragma unroll
            for (int mi = 0; mi < 4; ++mi) {
#pragma unroll
                for (int ni = 0; ni < 4; ++ni) {
                    asm volatile(
                        "mma.sync.aligned.m16n8k16.row.col.f32.f16.f16.f32 "
                        "{%0,%1,%2,%3}, {%4,%5,%6,%7}, {%8,%9}, {%0,%1,%2,%3};"
                        : "+f"(c[mi][ni][0]), "+f"(c[mi][ni][1]),
                          "+f"(c[mi][ni][2]), "+f"(c[mi][ni][3])
                        : "r"(af[cur][mi][0]), "r"(af[cur][mi][1]),
                          "r"(af[cur][mi][2]), "r"(af[cur][mi][3]),
                          "r"(bf[cur][ni][0]), "r"(bf[cur][ni][1]));
                }
            }
        }
    }

    // epilogue
#pragma unroll
    for (int mi = 0; mi < 4; ++mi) {
        const int r0 = (int)bm0 + wm * 64 + mi * 16 + (lane >> 2);
#pragma unroll
        for (int ni = 0; ni < 4; ++ni) {
            const int col = (int)bn0 + wn * 32 + ni * 8 + (lane & 3) * 2;
            *(float2*)&out[(size_t)r0 * N_DIM + col] =
                make_float2(c[mi][ni][0], c[mi][ni][1]);
            *(float2*)&out[(size_t)(r0 + 8) * N_DIM + col] =
                make_float2(c[mi][ni][2], c[mi][ni][3]);
        }
    }
}

// ---------------------------------------------------------------------------
extern "C" void kernel_launch(void* const* d_in, const int* in_sizes, int n_in,
                              void* d_out, int out_size) {
    const float* x      = (const float*)d_in[0];
    const int*   codes  = (const int*)d_in[1];
    const float* absmax = (const float*)d_in[2];
    float*       out    = (float*)d_out;

    {
        size_t total = W_T8 + X_T8;
        prep_kernel<<<(unsigned)((total + 255) / 256), 256>>>(x, codes, absmax);
    }
    cudaFuncSetAttribute(gemm_f16_kernel,
                         cudaFuncAttributeMaxDynamicSharedMemorySize, SMEM_BYTES);
    gemm_f16_kernel<<<NTILE * MTILE, 256, SMEM_BYTES>>>(out);
}

// round 17
// speedup vs baseline: 1.7610x; 1.0267x over previous
#include <cuda_runtime.h>
#include <cuda_fp16.h>
#include <cstdint>
#include <cstddef>

#define IN_F   4096
#define OUT_F  11008
#define M_DIM  8192
#define K_DIM  4096
#define N_DIM  11008

#define BM 128
#define BN 128
#define BK 64
#define NSTAGE 3
#define ASTR 72                 // BK + 8 halfword skew
#define ROWB (ASTR * 2)         // 144 B rows

#define NTILE (N_DIM / BN)      // 86
#define MTILE (M_DIM / BM)      // 64
#define GRP 8                   // M-panel raster

#define A_STAGE_BYTES (BM * ROWB)           // 18432
#define B_STAGE_BYTES (BN * ROWB)           // 18432
#define B_BASE (NSTAGE * A_STAGE_BYTES)
#define SMEM_BYTES (NSTAGE * (A_STAGE_BYTES + B_STAGE_BYTES))  // 110592

#define W_T8 ((size_t)OUT_F * IN_F / 8)
#define X_T8 ((size_t)M_DIM * K_DIM / 8)

__constant__ float c_nf4[16] = {
    -1.0f, -0.6961928009986877f, -0.5250730514526367f, -0.39491748809814453f,
    -0.28444138169288635f, -0.18477343022823334f, -0.09105003625154495f, 0.0f,
    0.07958029955625534f, 0.16093020141124725f, 0.24611230194568634f,
    0.33791524171829224f, 0.44070982933044434f, 0.5626170039176941f,
    0.7229568362236023f, 1.0f };

__device__ __align__(16) __half g_W[(size_t)OUT_F * IN_F];
__device__ __align__(16) __half g_X[(size_t)M_DIM * K_DIM];

// ---------------------------------------------------------------------------
// Kernel 1: fused prep — NF4 dequant (shared LUT) + x fp32->fp16.
// ---------------------------------------------------------------------------
__global__ void prep_kernel(const float* __restrict__ x,
                            const int* __restrict__ codes,
                            const float* __restrict__ absmax) {
    __shared__ float lut[16];
    if (threadIdx.x < 16) lut[threadIdx.x] = c_nf4[threadIdx.x];
    __syncthreads();
    size_t t = (size_t)blockIdx.x * blockDim.x + threadIdx.x;
    if (t < W_T8) {
        float am = absmax[t >> 3];
        int4 c0 = ((const int4*)codes)[2 * t];
        int4 c1 = ((const int4*)codes)[2 * t + 1];
        __half h[8];
        h[0] = __float2half(lut[c0.x] * am);
        h[1] = __float2half(lut[c0.y] * am);
        h[2] = __float2half(lut[c0.z] * am);
        h[3] = __float2half(lut[c0.w] * am);
        h[4] = __float2half(lut[c1.x] * am);
        h[5] = __float2half(lut[c1.y] * am);
        h[6] = __float2half(lut[c1.z] * am);
        h[7] = __float2half(lut[c1.w] * am);
        ((uint4*)g_W)[t] = *(const uint4*)h;
    } else {
        size_t u = t - W_T8;
        if (u < X_T8) {
            float4 a = ((const float4*)x)[2 * u];
            float4 b = ((const float4*)x)[2 * u + 1];
            __half h[8];
            h[0] = __float2half(a.x); h[1] = __float2half(a.y);
            h[2] = __float2half(a.z); h[3] = __float2half(a.w);
            h[4] = __float2half(b.x); h[5] = __float2half(b.y);
            h[6] = __float2half(b.z); h[7] = __float2half(b.w);
            ((uint4*)g_X)[u] = *(const uint4*)h;
        }
    }
}

// ---------------------------------------------------------------------------
// Kernel 2: fp16 GEMM. 128x128xBK64, 256 thr, 2 CTA/SM, 3-stage ring.
// cp.async issue is interleaved into the ks loop AFTER the first fragment
// loads, so LSU in-order dispatch never delays HMMA-feeding LDSMs.
// ---------------------------------------------------------------------------
__device__ __forceinline__ void cp16(uint32_t daddr, const void* src) {
    asm volatile("cp.async.cg.shared.global [%0], [%1], 16;" :: "r"(daddr), "l"(src) : "memory");
}

__device__ __forceinline__ uint32_t smem_u32(const void* p) {
    uint32_t a;
    asm("{ .reg .u64 t; cvta.to.shared.u64 t, %1; cvt.u32.u64 %0, t; }" : "=r"(a) : "l"(p));
    return a;
}

// half-stage producers: A (4 x cp16) and B (4 x cp16)
__device__ __forceinline__ void produce_A(uint32_t sa, const __half* Ag, int kt, int tid) {
    const __half* a = Ag + (size_t)kt * BK;
#pragma unroll
    for (int j = 0; j < 4; ++j) {
        int ch = tid + j * 256;
        int r = ch >> 3, c = ch & 7;
        cp16(sa + r * ROWB + c * 16, a + (size_t)r * K_DIM + c * 8);
    }
}
__device__ __forceinline__ void produce_B(uint32_t sb, const __half* Bg, int kt, int tid) {
    const __half* b = Bg + (size_t)kt * BK;
#pragma unroll
    for (int j = 0; j < 4; ++j) {
        int ch = tid + j * 256;
        int r = ch >> 3, c = ch & 7;
        cp16(sb + r * ROWB + c * 16, b + (size_t)r * K_DIM + c * 8);
    }
}

#define LDFRAG(slot, koff)                                                        \
    do {                                                                          \
        _Pragma("unroll")                                                         \
        for (int mi = 0; mi < 4; ++mi) {                                          \
            asm volatile("ldmatrix.sync.aligned.m8n8.x4.shared.b16 "              \
                         "{%0,%1,%2,%3}, [%4];"                                   \
                         : "=r"(af[slot][mi][0]), "=r"(af[slot][mi][1]),          \
                           "=r"(af[slot][mi][2]), "=r"(af[slot][mi][3])           \
                         : "r"(aaddr[mi] + (koff)));                              \
        }                                                                         \
        _Pragma("unroll")                                                         \
        for (int ni2 = 0; ni2 < 2; ++ni2) {                                       \
            asm volatile("ldmatrix.sync.aligned.m8n8.x4.shared.b16 "              \
                         "{%0,%1,%2,%3}, [%4];"                                   \
                         : "=r"(bf[slot][2 * ni2][0]), "=r"(bf[slot][2 * ni2][1]),\
                           "=r"(bf[slot][2 * ni2 + 1][0]),                        \
                           "=r"(bf[slot][2 * ni2 + 1][1])                         \
                         : "r"(baddr[ni2] + (koff)));                             \
        }                                                                         \
    } while (0)

#define HMMA_BLOCK(cur)                                                           \
    do {                                                                          \
        _Pragma("unroll")                                                         \
        for (int mi = 0; mi < 4; ++mi) {                                          \
            _Pragma("unroll")                                                     \
            for (int ni = 0; ni < 4; ++ni) {                                      \
                asm volatile(                                                     \
                    "mma.sync.aligned.m16n8k16.row.col.f32.f16.f16.f32 "          \
                    "{%0,%1,%2,%3}, {%4,%5,%6,%7}, {%8,%9}, {%0,%1,%2,%3};"       \
                    : "+f"(c[mi][ni][0]), "+f"(c[mi][ni][1]),                     \
                      "+f"(c[mi][ni][2]), "+f"(c[mi][ni][3])                      \
                    : "r"(af[cur][mi][0]), "r"(af[cur][mi][1]),                   \
                      "r"(af[cur][mi][2]), "r"(af[cur][mi][3]),                   \
                      "r"(bf[cur][ni][0]), "r"(bf[cur][ni][1]));                  \
            }                                                                     \
        }                                                                         \
    } while (0)

__global__ void __launch_bounds__(256, 2) gemm_f16_kernel(float* __restrict__ out) {
    extern __shared__ char smem[];
    const uint32_t sbase = smem_u32(smem);

    const int tid  = threadIdx.x;
    const int lane = tid & 31;
    const int warp = tid >> 5;
    const int wm   = warp >> 2;      // 0..1
    const int wn   = warp & 3;       // 0..3

    const int bid   = blockIdx.x;
    const int panel = bid / (GRP * NTILE);
    const int rem   = bid % (GRP * NTILE);
    const int bn    = rem / GRP;
    const int bm    = panel * GRP + (rem % GRP);

    const size_t bm0 = (size_t)bm * BM;
    const size_t bn0 = (size_t)bn * BN;
    const __half* Ag = g_X + bm0 * K_DIM;
    const __half* Bg = g_W + bn0 * K_DIM;

    float c[4][4][4];
#pragma unroll
    for (int i = 0; i < 4; ++i)
#pragma unroll
        for (int j = 0; j < 4; ++j)
#pragma unroll
            for (int r = 0; r < 4; ++r) c[i][j][r] = 0.0f;

    // prologue: stages 0,1 (full produce + commit each)
    produce_A(sbase, Ag, 0, tid);
    produce_B(sbase + B_BASE, Bg, 0, tid);
    asm volatile("cp.async.commit_group;" ::: "memory");
    produce_A(sbase + A_STAGE_BYTES, Ag, 1, tid);
    produce_B(sbase + B_BASE + B_STAGE_BYTES, Bg, 1, tid);
    asm volatile("cp.async.commit_group;" ::: "memory");

    const int NKT = K_DIM / BK;   // 64

    const int a_off = (wm * 64 + (lane & 15)) * ROWB + (lane >> 4) * 16;
    const int b_off = (wn * 32 + (lane & 7) + ((lane >> 4) & 1) * 8) * ROWB
                      + ((lane >> 3) & 1) * 16;

    for (int i = 0; i < NKT; ++i) {
        asm volatile("cp.async.wait_group 1;" ::: "memory");
        __syncthreads();

        const int buf = i % NSTAGE;
        const uint32_t sa = sbase + buf * A_STAGE_BYTES;
        const uint32_t sb = sbase + B_BASE + buf * B_STAGE_BYTES;

        uint32_t aaddr[4], baddr[2];
#pragma unroll
        for (int mi = 0; mi < 4; ++mi) aaddr[mi] = sa + a_off + mi * 16 * ROWB;
#pragma unroll
        for (int ni2 = 0; ni2 < 2; ++ni2) baddr[ni2] = sb + b_off + ni2 * 16 * ROWB;

        uint32_t af[2][4][4];
        uint32_t bf[2][4][2];

        // critical path first: fragments for ks=0
        LDFRAG(0, 0);

        const bool pf = (i + 2 < NKT);
        const int nb = (i + 2) % NSTAGE;

        // ks = 0: prefetch ks1 frags, then A-half of stage i+2, then HMMAs
        LDFRAG(1, 32);
        if (pf) produce_A(sbase + nb * A_STAGE_BYTES, Ag, i + 2, tid);
        HMMA_BLOCK(0);

        // ks = 1: prefetch ks2 frags, then B-half + commit, then HMMAs
        LDFRAG(0, 64);
        if (pf) produce_B(sbase + B_BASE + nb * B_STAGE_BYTES, Bg, i + 2, tid);
        if (pf) asm volatile("cp.async.commit_group;" ::: "memory");
        HMMA_BLOCK(1);

        // ks = 2: prefetch ks3 frags, then HMMAs
        LDFRAG(1, 96);
        HMMA_BLOCK(0);

        // ks = 3
        HMMA_BLOCK(1);
    }

    // epilogue
#pragma unroll
    for (int mi = 0; mi < 4; ++mi) {
        const int r0 = (int)bm0 + wm * 64 + mi * 16 + (lane >> 2);
#pragma unroll
        for (int ni = 0; ni < 4; ++ni) {
            const int col = (int)bn0 + wn * 32 + ni * 8 + (lane & 3) * 2;
            *(float2*)&out[(size_t)r0 * N_DIM + col] =
                make_float2(c[mi][ni][0], c[mi][ni][1]);
            *(float2*)&out[(size_t)(r0 + 8) * N_DIM + col] =
                make_float2(c[mi][ni][2], c[mi][ni][3]);
        }
    }
}

// ---------------------------------------------------------------------------
extern "C" void kernel_launch(void* const* d_in, const int* in_sizes, int n_in,
                              void* d_out, int out_size) {
    const float* x      = (const float*)d_in[0];
    const int*   codes  = (const int*)d_in[1];
    const float* absmax = (const float*)d_in[2];
    float*       out    = (float*)d_out;

    {
        size_t total = W_T8 + X_T8;
        prep_kernel<<<(unsigned)((total + 255) / 256), 256>>>(x, codes, absmax);
    }
    cudaFuncSetAttribute(gemm_f16_kernel,
                         cudaFuncAttributeMaxDynamicSharedMemorySize, SMEM_BYTES);
    gemm_f16_kernel<<<NTILE * MTILE, 256, SMEM_BYTES>>>(out);
}